// round 7
// baseline (speedup 1.0000x reference)
#include <cuda_runtime.h>
#include <math.h>

#define H 1024
#define V 50257
#define L 2
#define ROWS_PB 8
#define NB_LOGITS ((V + ROWS_PB - 1) / ROWS_PB)  // 6283

// Scratch (device globals; no allocation allowed)
__device__ float g_x[H];        // GRU layer 0 output
__device__ float g_y[H];        // GRU layer 1 output (logits input)
__device__ float g_gh1[3 * H];  // GRU layer 1 recurrent dots (hoisted)
__device__ float g_logits[V];
__device__ float g_sumexp;      // accumulated sum of exp(logit); reset in k1

__device__ __forceinline__ float warp_sum(float s) {
    #pragma unroll
    for (int o = 16; o > 0; o >>= 1) s += __shfl_xor_sync(0xFFFFFFFF, s, o);
    return s;
}
__device__ __forceinline__ float sigmoidf_(float v) {
    return 1.0f / (1.0f + __expf(-v));
}

__device__ __forceinline__ float dot_row_vec(const float4* __restrict__ wr,
                                             const float4* __restrict__ vv,
                                             int lane, bool do_relu) {
    float4 a[8], b[8];
    #pragma unroll
    for (int k = 0; k < 8; k++) a[k] = __ldcs(&wr[lane + 32 * k]);
    #pragma unroll
    for (int k = 0; k < 8; k++) b[k] = __ldg(&vv[lane + 32 * k]);
    if (do_relu) {
        #pragma unroll
        for (int k = 0; k < 8; k++) {
            b[k].x = fmaxf(b[k].x, 0.0f); b[k].y = fmaxf(b[k].y, 0.0f);
            b[k].z = fmaxf(b[k].z, 0.0f); b[k].w = fmaxf(b[k].w, 0.0f);
        }
    }
    float s = 0.0f;
    #pragma unroll
    for (int k = 0; k < 8; k++)
        s += a[k].x * b[k].x + a[k].y * b[k].y + a[k].z * b[k].z + a[k].w * b[k].w;
    return warp_sum(s);
}

// ---- K1: GRU layer 0 (emb+relu fused) + hoisted GRU1 w_hh half ----
// grid = H + H/2 blocks, 192 threads (6 warps).
// bid <  H           : GRU0 for j=bid (6 dots + gates)
// bid in [H, H+H/2)  : gh1 dots for j = 2*(bid-H) + {0,1}, 3 gates each
__global__ __launch_bounds__(192) void k1_kernel(
    const long long* __restrict__ idx,
    const float* __restrict__ emb,
    const float* __restrict__ hidden,    // [L, H]
    const float* __restrict__ w_ih0,     // [3H, H]
    const float* __restrict__ w_hh0,     // [3H, H]
    const float* __restrict__ b_ih0,     // [3H]
    const float* __restrict__ b_hh0,     // [3H]
    const float* __restrict__ w_hh1,     // [3H, H]
    float* __restrict__ out_hidden0)     // d_out slice, layer 0
{
    int w = threadIdx.x >> 5;
    int lane = threadIdx.x & 31;

    if (blockIdx.x >= H) {
        // hoisted GRU1 recurrent dots: no dependence on GRU0
        int jj = blockIdx.x - H;            // 0..511
        int j = jj * 2 + (w / 3);           // two j's per block
        int gate = w % 3;
        const float4* wr = reinterpret_cast<const float4*>(
            w_hh1 + (size_t)(gate * H + j) * H);
        const float4* vv = reinterpret_cast<const float4*>(hidden + H);
        float s = dot_row_vec(wr, vv, lane, false);
        if (lane == 0) g_gh1[gate * H + j] = s;
        return;
    }

    if (blockIdx.x == 0 && threadIdx.x == 32) {
        g_sumexp = 0.0f;  // reset accumulator each replay (before logits runs)
    }

    int j = blockIdx.x;
    const float* vec = (w < 3) ? (emb + (size_t)idx[0] * H) : hidden;
    const float* W   = (w < 3) ? w_ih0 : w_hh0;
    int row = (w % 3) * H + j;

    float s = dot_row_vec(reinterpret_cast<const float4*>(W + (size_t)row * H),
                          reinterpret_cast<const float4*>(vec),
                          lane, /*relu on emb*/ w < 3);

    __shared__ float sm[6];
    if (lane == 0) sm[w] = s;
    __syncthreads();

    if (threadIdx.x == 0) {
        float i_r = sm[0] + b_ih0[j];
        float i_z = sm[1] + b_ih0[H + j];
        float i_n = sm[2] + b_ih0[2 * H + j];
        float h_r = sm[3] + b_hh0[j];
        float h_z = sm[4] + b_hh0[H + j];
        float h_n = sm[5] + b_hh0[2 * H + j];
        float r = sigmoidf_(i_r + h_r);
        float z = sigmoidf_(i_z + h_z);
        float n = tanhf(i_n + r * h_n);
        float hn = (1.0f - z) * n + z * hidden[j];
        g_x[j] = hn;
        out_hidden0[j] = hn;
    }
}

// ---- K2: GRU1 finish — w_ih1 @ g_x (3 dots) + gate combine with g_gh1 ----
// grid = H blocks, 96 threads (3 warps).
__global__ __launch_bounds__(96) void k2_kernel(
    const float* __restrict__ hidden,    // [L, H]
    const float* __restrict__ w_ih1,     // [3H, H]
    const float* __restrict__ b_ih1,     // [3H]
    const float* __restrict__ b_hh1,     // [3H]
    float* __restrict__ out_hidden1)     // d_out slice, layer 1
{
    int j = blockIdx.x;
    int w = threadIdx.x >> 5;
    int lane = threadIdx.x & 31;

    const float4* wr = reinterpret_cast<const float4*>(
        w_ih1 + (size_t)(w * H + j) * H);
    const float4* vv = reinterpret_cast<const float4*>(g_x);
    float s = dot_row_vec(wr, vv, lane, false);

    __shared__ float sm[3];
    if (lane == 0) sm[w] = s;
    __syncthreads();

    if (threadIdx.x == 0) {
        float i_r = sm[0] + b_ih1[j];
        float i_z = sm[1] + b_ih1[H + j];
        float i_n = sm[2] + b_ih1[2 * H + j];
        float h_r = g_gh1[j]         + b_hh1[j];
        float h_z = g_gh1[H + j]     + b_hh1[H + j];
        float h_n = g_gh1[2 * H + j] + b_hh1[2 * H + j];
        float r = sigmoidf_(i_r + h_r);
        float z = sigmoidf_(i_z + h_z);
        float n = tanhf(i_n + r * h_n);
        float hn = (1.0f - z) * n + z * hidden[H + j];
        g_y[j] = hn;
        out_hidden1[j] = hn;
    }
}

// ---- logits = w_out @ y + b_out; y read via __ldg (no smem staging barrier).
// Epilogue: block sumexp via one atomicAdd (logits tiny, no max-shift needed). ----
__global__ __launch_bounds__(256) void logits_kernel(
    const float* __restrict__ w_out,
    const float* __restrict__ b_out)
{
    __shared__ float rowv[ROWS_PB];

    int wid = threadIdx.x >> 5;
    int lane = threadIdx.x & 31;
    int row = blockIdx.x * ROWS_PB + wid;

    float val = 0.0f;
    bool valid = (row < V);
    if (valid) {
        const float4* wr = reinterpret_cast<const float4*>(w_out + (size_t)row * H);
        const float4* vv = reinterpret_cast<const float4*>(g_y);
        float s = dot_row_vec(wr, vv, lane, false);
        if (lane == 0) {
            val = s + b_out[row];
            g_logits[row] = val;
        }
    }
    if (lane == 0) rowv[wid] = valid ? expf(val) : 0.0f;
    __syncthreads();

    if (threadIdx.x < 32) {
        float e = (lane < ROWS_PB) ? rowv[lane] : 0.0f;
        float sum = warp_sum(e);
        if (lane == 0) atomicAdd(&g_sumexp, sum);
    }
}

// ---- write logprobs: out[i] = logits[i] - log(sumexp), float4 wide ----
__global__ __launch_bounds__(256) void write_kernel(float* __restrict__ out) {
    float c = logf(g_sumexp);
    int i = blockIdx.x * 256 + threadIdx.x;
    const int V4 = V / 4;  // 12564
    if (i < V4) {
        float4 v = reinterpret_cast<const float4*>(g_logits)[i];
        v.x -= c; v.y -= c; v.z -= c; v.w -= c;
        reinterpret_cast<float4*>(out)[i] = v;
    }
    if (i == 0) out[V - 1] = g_logits[V - 1] - c;  // tail (V % 4 == 1)
}

extern "C" void kernel_launch(void* const* d_in, const int* in_sizes, int n_in,
                              void* d_out, int out_size) {
    const long long* idx  = (const long long*)d_in[0];
    const float* hidden   = (const float*)d_in[1];
    const float* emb      = (const float*)d_in[2];
    const float* w_ih     = (const float*)d_in[3];
    const float* w_hh     = (const float*)d_in[4];
    const float* b_ih     = (const float*)d_in[5];
    const float* b_hh     = (const float*)d_in[6];
    const float* w_out    = (const float*)d_in[7];
    const float* b_out    = (const float*)d_in[8];

    float* out = (float*)d_out;
    float* out_logprobs = out;       // [V]
    float* out_hidden   = out + V;   // [L, 1, H]

    // K1: GRU0 + hoisted GRU1 recurrent half
    k1_kernel<<<H + H / 2, 192>>>(idx, emb, hidden,
                                  w_ih, w_hh, b_ih, b_hh,
                                  w_hh + 3 * H * H,
                                  out_hidden);

    // K2: GRU1 finish
    k2_kernel<<<H, 96>>>(hidden,
                         w_ih + 3 * H * H,
                         b_ih + 3 * H, b_hh + 3 * H,
                         out_hidden + H);

    // K3: vocab projection + sumexp accumulation
    logits_kernel<<<NB_LOGITS, 256>>>(w_out, b_out);

    // K4: final logprobs
    write_kernel<<<(V / 4 + 255) / 256, 256>>>(out_logprobs);
}

// round 8
// speedup vs baseline: 1.0372x; 1.0372x over previous
#include <cuda_runtime.h>
#include <math.h>

#define H 1024
#define V 50257
#define L 2
#define ROWS_PB 16
#define NB_LOGITS ((V + ROWS_PB - 1) / ROWS_PB)  // 3142

// Scratch (device globals; no allocation allowed)
__device__ float g_x[H];        // GRU layer 0 output
__device__ float g_y[H];        // GRU layer 1 output (logits input)
__device__ float g_logits[V];
__device__ float g_sumexp;      // accumulated sum of exp(logit); reset by gru0

__device__ __forceinline__ float warp_sum(float s) {
    #pragma unroll
    for (int o = 16; o > 0; o >>= 1) s += __shfl_xor_sync(0xFFFFFFFF, s, o);
    return s;
}
__device__ __forceinline__ float sigmoidf_(float v) {
    return 1.0f / (1.0f + __expf(-v));
}

// ---- GRU layer. grid = H blocks, 192 threads (6 warps). ----
template<bool FUSE_EMB>
__global__ __launch_bounds__(192) void gru_layer_kernel(
    const long long* __restrict__ idx,
    const float* __restrict__ emb,
    const float* __restrict__ x_vec,
    const float* __restrict__ h_prev,
    const float* __restrict__ w_ih,
    const float* __restrict__ w_hh,
    const float* __restrict__ b_ih,
    const float* __restrict__ b_hh,
    float* __restrict__ h_out_scratch,
    float* __restrict__ h_out_final)
{
    if (FUSE_EMB && blockIdx.x == 0 && threadIdx.x == 32) {
        g_sumexp = 0.0f;  // reset accumulator each replay (before logits runs)
    }

    int j = blockIdx.x;
    int w = threadIdx.x >> 5;
    int lane = threadIdx.x & 31;

    const float* vec;
    bool do_relu = false;
    if (w < 3) {
        if (FUSE_EMB) { vec = emb + (size_t)idx[0] * H; do_relu = true; }
        else          { vec = x_vec; }
    } else {
        vec = h_prev;
    }
    const float* W = (w < 3) ? w_ih : w_hh;
    int row = (w % 3) * H + j;

    const float4* wr = reinterpret_cast<const float4*>(W + (size_t)row * H);
    const float4* vv = reinterpret_cast<const float4*>(vec);

    float4 a[8], b[8];
    #pragma unroll
    for (int k = 0; k < 8; k++) a[k] = __ldcs(&wr[lane + 32 * k]);
    #pragma unroll
    for (int k = 0; k < 8; k++) b[k] = __ldg(&vv[lane + 32 * k]);
    if (do_relu) {
        #pragma unroll
        for (int k = 0; k < 8; k++) {
            b[k].x = fmaxf(b[k].x, 0.0f); b[k].y = fmaxf(b[k].y, 0.0f);
            b[k].z = fmaxf(b[k].z, 0.0f); b[k].w = fmaxf(b[k].w, 0.0f);
        }
    }
    float s = 0.0f;
    #pragma unroll
    for (int k = 0; k < 8; k++)
        s += a[k].x * b[k].x + a[k].y * b[k].y + a[k].z * b[k].z + a[k].w * b[k].w;
    s = warp_sum(s);

    __shared__ float sm[6];
    if (lane == 0) sm[w] = s;
    __syncthreads();

    if (threadIdx.x == 0) {
        float i_r = sm[0] + b_ih[j];
        float i_z = sm[1] + b_ih[H + j];
        float i_n = sm[2] + b_ih[2 * H + j];
        float h_r = sm[3] + b_hh[j];
        float h_z = sm[4] + b_hh[H + j];
        float h_n = sm[5] + b_hh[2 * H + j];
        float r = sigmoidf_(i_r + h_r);
        float z = sigmoidf_(i_z + h_z);
        float n = tanhf(i_n + r * h_n);
        float hn = (1.0f - z) * n + z * h_prev[j];
        h_out_scratch[j] = hn;
        h_out_final[j]   = hn;
    }
}

// ---- logits = w_out @ y + b_out. 256 threads, 8 warps, 2 rows per warp.
// 16 independent weight LDG.128 per thread in flight. smem-staged y.
// Epilogue: block sumexp via one atomicAdd (logits tiny, no max-shift). ----
__global__ __launch_bounds__(256) void logits_kernel(
    const float* __restrict__ w_out,
    const float* __restrict__ b_out)
{
    __shared__ float xs[H];
    __shared__ float rowv[ROWS_PB];
    for (int i = threadIdx.x; i < H; i += 256) xs[i] = g_y[i];
    __syncthreads();

    int wid = threadIdx.x >> 5;
    int lane = threadIdx.x & 31;
    int row0 = blockIdx.x * ROWS_PB + wid * 2;
    int row1 = row0 + 1;

    bool v0 = (row0 < V);
    bool v1 = (row1 < V);

    const float4* wr0 = reinterpret_cast<const float4*>(w_out + (size_t)row0 * H);
    const float4* wr1 = reinterpret_cast<const float4*>(w_out + (size_t)row1 * H);
    const float4* vv  = reinterpret_cast<const float4*>(xs);

    float4 a0[8], a1[8];
    if (v0) {
        #pragma unroll
        for (int k = 0; k < 8; k++) a0[k] = __ldcs(&wr0[lane + 32 * k]);
    }
    if (v1) {
        #pragma unroll
        for (int k = 0; k < 8; k++) a1[k] = __ldcs(&wr1[lane + 32 * k]);
    }

    float s0 = 0.0f, s1 = 0.0f;
    #pragma unroll
    for (int k = 0; k < 8; k++) {
        float4 b = vv[lane + 32 * k];
        if (v0) s0 += a0[k].x * b.x + a0[k].y * b.y + a0[k].z * b.z + a0[k].w * b.w;
        if (v1) s1 += a1[k].x * b.x + a1[k].y * b.y + a1[k].z * b.z + a1[k].w * b.w;
    }
    s0 = warp_sum(s0);
    s1 = warp_sum(s1);

    if (lane == 0) {
        float e0 = 0.0f, e1 = 0.0f;
        if (v0) {
            float val0 = s0 + b_out[row0];
            g_logits[row0] = val0;
            e0 = expf(val0);
        }
        if (v1) {
            float val1 = s1 + b_out[row1];
            g_logits[row1] = val1;
            e1 = expf(val1);
        }
        rowv[wid * 2]     = e0;
        rowv[wid * 2 + 1] = e1;
    }
    __syncthreads();

    // warp 0: sum the 16 per-row exps, single atomicAdd
    if (threadIdx.x < 32) {
        float e = (lane < ROWS_PB) ? rowv[lane] : 0.0f;
        float sum = warp_sum(e);
        if (lane == 0) atomicAdd(&g_sumexp, sum);
    }
}

// ---- write logprobs: out[i] = logits[i] - log(sumexp), float4 wide ----
__global__ __launch_bounds__(256) void write_kernel(float* __restrict__ out) {
    float c = logf(g_sumexp);
    int i = blockIdx.x * 256 + threadIdx.x;
    const int V4 = V / 4;  // 12564
    if (i < V4) {
        float4 v = reinterpret_cast<const float4*>(g_logits)[i];
        v.x -= c; v.y -= c; v.z -= c; v.w -= c;
        reinterpret_cast<float4*>(out)[i] = v;
    }
    if (i == 0) out[V - 1] = g_logits[V - 1] - c;  // tail (V % 4 == 1)
}

extern "C" void kernel_launch(void* const* d_in, const int* in_sizes, int n_in,
                              void* d_out, int out_size) {
    const long long* idx  = (const long long*)d_in[0];
    const float* hidden   = (const float*)d_in[1];
    const float* emb      = (const float*)d_in[2];
    const float* w_ih     = (const float*)d_in[3];
    const float* w_hh     = (const float*)d_in[4];
    const float* b_ih     = (const float*)d_in[5];
    const float* b_hh     = (const float*)d_in[6];
    const float* w_out    = (const float*)d_in[7];
    const float* b_out    = (const float*)d_in[8];

    float* out = (float*)d_out;
    float* out_logprobs = out;       // [V]
    float* out_hidden   = out + V;   // [L, 1, H]

    float* g_x_ptr; cudaGetSymbolAddress((void**)&g_x_ptr, g_x);
    float* g_y_ptr; cudaGetSymbolAddress((void**)&g_y_ptr, g_y);

    gru_layer_kernel<true><<<H, 192>>>(idx, emb, nullptr, hidden,
                                       w_ih, w_hh, b_ih, b_hh,
                                       g_x_ptr, out_hidden);

    gru_layer_kernel<false><<<H, 192>>>(idx, emb, g_x_ptr, hidden + H,
                                        w_ih + 3 * H * H, w_hh + 3 * H * H,
                                        b_ih + 3 * H, b_hh + 3 * H,
                                        g_y_ptr, out_hidden + H);

    logits_kernel<<<NB_LOGITS, 256>>>(w_out, b_out);

    write_kernel<<<(V / 4 + 255) / 256, 256>>>(out_logprobs);
}